// round 2
// baseline (speedup 1.0000x reference)
#include <cuda_runtime.h>
#include <cstdint>

// Problem constants (fixed by the dataset)
#define NN 50000
#define HH 64
#define EE 800000

// Scratch: a1|a2 accumulators (2*N*H) and intermediate h (N*H)
__device__ float g_acc[2 * NN * HH];
__device__ float g_h[NN * HH];

// ---------------------------------------------------------------------------
// Zero the accumulators
// ---------------------------------------------------------------------------
__global__ void zero_kernel(float4* __restrict__ p, int n4) {
    int i = blockIdx.x * blockDim.x + threadIdx.x;
    if (i < n4) p[i] = make_float4(0.f, 0.f, 0.f, 0.f);
}

// ---------------------------------------------------------------------------
// Scatter: for each edge e of each relation r:
//   a_r[dst[e]] += feat_r[e] * h[src[e]]
// Half-warp (16 lanes) per edge, float4 per lane, red.global.add.v4.f32.
// ---------------------------------------------------------------------------
__global__ void scatter_kernel(const float* __restrict__ h,
                               const float* __restrict__ feat1,
                               const float* __restrict__ feat2,
                               const int*   __restrict__ src1,
                               const int*   __restrict__ dst1,
                               const int*   __restrict__ src2,
                               const int*   __restrict__ dst2,
                               float* __restrict__ a1,
                               float* __restrict__ a2,
                               int E) {
    long long gid = (long long)blockIdx.x * blockDim.x + threadIdx.x;
    int lane16 = (int)(gid & 15);
    long long eid = gid >> 4;
    if (eid >= 2LL * E) return;

    const float* feat;
    const int*   src;
    const int*   dst;
    float*       out;
    int e;
    if (eid < E) {
        e = (int)eid;       feat = feat1; src = src1; dst = dst1; out = a1;
    } else {
        e = (int)(eid - E); feat = feat2; src = src2; dst = dst2; out = a2;
    }

    int s = __ldg(src + e);
    int d = __ldg(dst + e);

    const float4 hv = *(const float4*)(h    + (size_t)s * HH + lane16 * 4);
    const float4 fv = *(const float4*)(feat + (size_t)e * HH + lane16 * 4);

    float4 r;
    r.x = hv.x * fv.x;
    r.y = hv.y * fv.y;
    r.z = hv.z * fv.z;
    r.w = hv.w * fv.w;

    float* p = out + (size_t)d * HH + lane16 * 4;
    asm volatile("red.global.add.v4.f32 [%0], {%1, %2, %3, %4};"
                 :: "l"(p), "f"(r.x), "f"(r.y), "f"(r.z), "f"(r.w)
                 : "memory");
}

// ---------------------------------------------------------------------------
// Update: h_out = h_in + relu(concat(a1,a2) @ W + b)
// W: [128,64] row-major in smem. Persistent blocks, 4 nodes per block-iter.
// ---------------------------------------------------------------------------
__global__ void update_kernel(const float* __restrict__ h_in,
                              const float* __restrict__ a1,
                              const float* __restrict__ a2,
                              const float* __restrict__ W,
                              const float* __restrict__ b,
                              float* __restrict__ h_out,
                              int N) {
    __shared__ float Ws[128 * 64];
    __shared__ float bs[64];
    __shared__ float as[4][128];

    for (int i = threadIdx.x; i < 128 * 64; i += blockDim.x) Ws[i] = W[i];
    if (threadIdx.x < 64) bs[threadIdx.x] = b[threadIdx.x];
    __syncthreads();

    const int sub = threadIdx.x >> 6;   // 0..3 (node within group)
    const int col = threadIdx.x & 63;   // output column

    for (int base = blockIdx.x * 4; base < N; base += gridDim.x * 4) {
        // Cooperative load of 4 concat-rows (4 x 128 floats)
        for (int i = threadIdx.x; i < 512; i += 256) {
            int nd = i >> 7;
            int k  = i & 127;
            int nn = base + nd;
            float v = 0.f;
            if (nn < N)
                v = (k < 64) ? a1[(size_t)nn * HH + k]
                             : a2[(size_t)nn * HH + (k - 64)];
            as[nd][k] = v;
        }
        __syncthreads();

        int node = base + sub;
        if (node < N) {
            float acc = bs[col];
            #pragma unroll 16
            for (int k = 0; k < 128; k++)
                acc = fmaf(as[sub][k], Ws[k * 64 + col], acc);
            acc = fmaxf(acc, 0.f);
            h_out[(size_t)node * HH + col] = h_in[(size_t)node * HH + col] + acc;
        }
        __syncthreads();
    }
}

// ---------------------------------------------------------------------------
// Launch
// ---------------------------------------------------------------------------
extern "C" void kernel_launch(void* const* d_in, const int* in_sizes, int n_in,
                              void* d_out, int out_size) {
    const float* h0    = (const float*)d_in[0];   // [N,64]
    const float* feat1 = (const float*)d_in[1];   // [E,64]
    const float* feat2 = (const float*)d_in[2];   // [E,64]
    const float* W1    = (const float*)d_in[3];   // [128,64]
    const float* b1    = (const float*)d_in[4];   // [64]
    const float* W2    = (const float*)d_in[5];   // [128,64]
    const float* b2    = (const float*)d_in[6];   // [64]
    const int*   src1  = (const int*)d_in[7];     // [E]
    const int*   dst1  = (const int*)d_in[8];
    const int*   src2  = (const int*)d_in[9];
    const int*   dst2  = (const int*)d_in[10];
    float* out = (float*)d_out;

    const int N = in_sizes[0] / HH;   // 50000
    const int E = in_sizes[7];        // 800000

    float* acc_base;
    float* hbuf;
    cudaGetSymbolAddress((void**)&acc_base, g_acc);
    cudaGetSymbolAddress((void**)&hbuf, g_h);
    float* a1 = acc_base;
    float* a2 = acc_base + (size_t)N * HH;

    const int n4 = 2 * N * HH / 4;
    const int zgrid = (n4 + 255) / 256;

    const long long tot_threads = 2LL * E * 16;
    const int sgrid = (int)((tot_threads + 255) / 256);

    const int ugrid = 888;  // 6 blocks/SM x 148 SMs (persistent-ish)

    // ---- Layer 1 ----
    zero_kernel<<<zgrid, 256>>>((float4*)acc_base, n4);
    scatter_kernel<<<sgrid, 256>>>(h0, feat1, feat2, src1, dst1, src2, dst2,
                                   a1, a2, E);
    update_kernel<<<ugrid, 256>>>(h0, a1, a2, W1, b1, hbuf, N);

    // ---- Layer 2 ----
    zero_kernel<<<zgrid, 256>>>((float4*)acc_base, n4);
    scatter_kernel<<<sgrid, 256>>>(hbuf, feat1, feat2, src1, dst1, src2, dst2,
                                   a1, a2, E);
    update_kernel<<<ugrid, 256>>>(hbuf, a1, a2, W2, b2, out, N);
}

// round 3
// speedup vs baseline: 1.3399x; 1.3399x over previous
#include <cuda_runtime.h>
#include <cstdint>

#define NN 50000
#define HH 64
#define EE 800000

// Scratch: a1|a2 accumulators (2*N*H) and intermediate h (N*H)
__device__ float g_acc[2 * NN * HH];
__device__ float g_h[NN * HH];

// ---------------------------------------------------------------------------
// Zero the accumulators (layer 1 only; layer 2's zeroing is fused into update)
// ---------------------------------------------------------------------------
__global__ void zero_kernel(float4* __restrict__ p, int n4) {
    int i = blockIdx.x * blockDim.x + threadIdx.x;
    if (i < n4) p[i] = make_float4(0.f, 0.f, 0.f, 0.f);
}

// ---------------------------------------------------------------------------
// Scatter: a_r[dst[e]] += feat_r[e] * h[src[e]]  (both relations in one grid)
// Half-warp (16 lanes) per edge, float4 per lane, red.global.add.v4.f32.
// ---------------------------------------------------------------------------
__global__ void scatter_kernel(const float* __restrict__ h,
                               const float* __restrict__ feat1,
                               const float* __restrict__ feat2,
                               const int*   __restrict__ src1,
                               const int*   __restrict__ dst1,
                               const int*   __restrict__ src2,
                               const int*   __restrict__ dst2,
                               float* __restrict__ a1,
                               float* __restrict__ a2,
                               int E) {
    long long gid = (long long)blockIdx.x * blockDim.x + threadIdx.x;
    int lane16 = (int)(gid & 15);
    long long eid = gid >> 4;
    if (eid >= 2LL * E) return;

    const float* feat;
    const int*   src;
    const int*   dst;
    float*       out;
    int e;
    if (eid < E) {
        e = (int)eid;       feat = feat1; src = src1; dst = dst1; out = a1;
    } else {
        e = (int)(eid - E); feat = feat2; src = src2; dst = dst2; out = a2;
    }

    int s = __ldg(src + e);
    int d = __ldg(dst + e);

    const float4 hv = *(const float4*)(h    + (size_t)s * HH + lane16 * 4);
    const float4 fv = *(const float4*)(feat + (size_t)e * HH + lane16 * 4);

    float4 r;
    r.x = hv.x * fv.x;
    r.y = hv.y * fv.y;
    r.z = hv.z * fv.z;
    r.w = hv.w * fv.w;

    float* p = out + (size_t)d * HH + lane16 * 4;
    asm volatile("red.global.add.v4.f32 [%0], {%1, %2, %3, %4};"
                 :: "l"(p), "f"(r.x), "f"(r.y), "f"(r.z), "f"(r.w)
                 : "memory");
}

// ---------------------------------------------------------------------------
// Update: h_out = h_in + relu(concat(a1,a2) @ W + b)
// Register-tiled: block tile = 64 nodes x 64 cols, thread tile = 4 nodes x 4
// cols (float4). W[128,64] and the A-tile live in smem; A rows padded to 132
// floats for conflict-free LDS. ZERO_ACC: write zeros back to a1/a2 after
// consuming them (prepares next layer's accumulation, replaces zero_kernel).
// ---------------------------------------------------------------------------
#define APAD 132
#define UPD_SMEM_BYTES ((128 * 64 + 64 * APAD) * 4)

template <bool ZERO_ACC>
__global__ void update_kernel(const float* __restrict__ h_in,
                              float* __restrict__ a1,
                              float* __restrict__ a2,
                              const float* __restrict__ W,
                              const float* __restrict__ b,
                              float* __restrict__ h_out,
                              int N) {
    extern __shared__ float smem[];
    float* Ws = smem;                       // [128][64]
    float (*As)[APAD] = (float (*)[APAD])(smem + 128 * 64);  // [64][APAD]

    const int tid = threadIdx.x;
    const int tc  = tid & 15;   // col group: cols 4*tc .. 4*tc+3
    const int tn  = tid >> 4;   // node group: nodes 4*tn .. 4*tn+3

    // Load W into smem (2048 float4, 8 per thread)
    for (int i = tid; i < 128 * 16; i += 256)
        ((float4*)Ws)[i] = ((const float4*)W)[i];

    const float4 bias = ((const float4*)b)[tc];

    const int base = blockIdx.x * 64;

    // Load A-tile: 64 nodes x 128 k  (k<64 from a1, k>=64 from a2)
    for (int i = tid; i < 2048; i += 256) {
        int node = i >> 5;       // 0..63
        int kq   = i & 31;       // float4 index 0..31
        int gn   = base + node;
        float4 v = make_float4(0.f, 0.f, 0.f, 0.f);
        if (gn < N) {
            if (kq < 16) v = ((const float4*)(a1 + (size_t)gn * HH))[kq];
            else         v = ((const float4*)(a2 + (size_t)gn * HH))[kq - 16];
        }
        *(float4*)&As[node][kq * 4] = v;
    }
    __syncthreads();

    if (ZERO_ACC) {
        const float4 z = make_float4(0.f, 0.f, 0.f, 0.f);
        for (int i = tid; i < 2048; i += 256) {
            int node = i >> 5;
            int kq   = i & 31;
            int gn   = base + node;
            if (gn < N) {
                if (kq < 16) ((float4*)(a1 + (size_t)gn * HH))[kq] = z;
                else         ((float4*)(a2 + (size_t)gn * HH))[kq - 16] = z;
            }
        }
    }

    float4 acc[4];
    #pragma unroll
    for (int i = 0; i < 4; i++) acc[i] = bias;

    #pragma unroll 4
    for (int k4 = 0; k4 < 32; k4++) {
        const int k = k4 * 4;
        float4 w0 = *(const float4*)&Ws[(k + 0) * 64 + tc * 4];
        float4 w1 = *(const float4*)&Ws[(k + 1) * 64 + tc * 4];
        float4 w2 = *(const float4*)&Ws[(k + 2) * 64 + tc * 4];
        float4 w3 = *(const float4*)&Ws[(k + 3) * 64 + tc * 4];
        #pragma unroll
        for (int i = 0; i < 4; i++) {
            float4 a = *(const float4*)&As[tn * 4 + i][k];
            acc[i].x = fmaf(a.w, w3.x, fmaf(a.z, w2.x, fmaf(a.y, w1.x, fmaf(a.x, w0.x, acc[i].x))));
            acc[i].y = fmaf(a.w, w3.y, fmaf(a.z, w2.y, fmaf(a.y, w1.y, fmaf(a.x, w0.y, acc[i].y))));
            acc[i].z = fmaf(a.w, w3.z, fmaf(a.z, w2.z, fmaf(a.y, w1.z, fmaf(a.x, w0.z, acc[i].z))));
            acc[i].w = fmaf(a.w, w3.w, fmaf(a.z, w2.w, fmaf(a.y, w1.w, fmaf(a.x, w0.w, acc[i].w))));
        }
    }

    // Epilogue: relu + residual
    #pragma unroll
    for (int i = 0; i < 4; i++) {
        int gn = base + tn * 4 + i;
        if (gn < N) {
            float4 hv = ((const float4*)(h_in + (size_t)gn * HH))[tc];
            float4 o;
            o.x = hv.x + fmaxf(acc[i].x, 0.f);
            o.y = hv.y + fmaxf(acc[i].y, 0.f);
            o.z = hv.z + fmaxf(acc[i].z, 0.f);
            o.w = hv.w + fmaxf(acc[i].w, 0.f);
            ((float4*)(h_out + (size_t)gn * HH))[tc] = o;
        }
    }
}

// ---------------------------------------------------------------------------
// Launch
// ---------------------------------------------------------------------------
extern "C" void kernel_launch(void* const* d_in, const int* in_sizes, int n_in,
                              void* d_out, int out_size) {
    const float* h0    = (const float*)d_in[0];
    const float* feat1 = (const float*)d_in[1];
    const float* feat2 = (const float*)d_in[2];
    const float* W1    = (const float*)d_in[3];
    const float* b1    = (const float*)d_in[4];
    const float* W2    = (const float*)d_in[5];
    const float* b2    = (const float*)d_in[6];
    const int*   src1  = (const int*)d_in[7];
    const int*   dst1  = (const int*)d_in[8];
    const int*   src2  = (const int*)d_in[9];
    const int*   dst2  = (const int*)d_in[10];
    float* out = (float*)d_out;

    const int N = in_sizes[0] / HH;
    const int E = in_sizes[7];

    float* acc_base;
    float* hbuf;
    cudaGetSymbolAddress((void**)&acc_base, g_acc);
    cudaGetSymbolAddress((void**)&hbuf, g_h);
    float* a1 = acc_base;
    float* a2 = acc_base + (size_t)N * HH;

    static bool attr_set = false;
    if (!attr_set) {
        cudaFuncSetAttribute(update_kernel<true>,
                             cudaFuncAttributeMaxDynamicSharedMemorySize,
                             UPD_SMEM_BYTES);
        cudaFuncSetAttribute(update_kernel<false>,
                             cudaFuncAttributeMaxDynamicSharedMemorySize,
                             UPD_SMEM_BYTES);
        attr_set = true;
    }

    const int n4 = 2 * N * HH / 4;
    const int zgrid = (n4 + 255) / 256;

    const long long tot_threads = 2LL * E * 16;
    const int sgrid = (int)((tot_threads + 255) / 256);

    const int ugrid = (N + 63) / 64;   // 782 tiles

    // ---- Layer 1 ----
    zero_kernel<<<zgrid, 256>>>((float4*)acc_base, n4);
    scatter_kernel<<<sgrid, 256>>>(h0, feat1, feat2, src1, dst1, src2, dst2,
                                   a1, a2, E);
    update_kernel<true><<<ugrid, 256, UPD_SMEM_BYTES>>>(h0, a1, a2, W1, b1,
                                                        hbuf, N);

    // ---- Layer 2 ----
    scatter_kernel<<<sgrid, 256>>>(hbuf, feat1, feat2, src1, dst1, src2, dst2,
                                   a1, a2, E);
    update_kernel<false><<<ugrid, 256, UPD_SMEM_BYTES>>>(hbuf, a1, a2, W2, b2,
                                                         out, N);
}

// round 4
// speedup vs baseline: 1.4284x; 1.0660x over previous
#include <cuda_runtime.h>
#include <cstdint>

#define NN 50000
#define HH 64
#define EE 800000
#define MM (2 * NN)            // total (rel, node) bins
#define SCAN_BLK 1024
#define NB ((MM + SCAN_BLK - 1) / SCAN_BLK)   // 98 scan blocks

// Scratch
__device__ float g_acc[2 * NN * HH];   // a1 | a2  (indexed by rel*N+n)
__device__ float g_h[NN * HH];         // intermediate h
__device__ int   g_cnt[MM];            // per-bin degree
__device__ int   g_ofs[MM + 1];        // CSR offsets
__device__ int   g_cur[MM];            // fill cursors
__device__ int   g_part[NB + 1];       // scan partials
__device__ int2  g_sorted[2 * EE];     // {edge_id, src} sorted by (rel, dst)

// ---------------------------------------------------------------------------
// CSR build: zero counts -> histogram -> scan -> fill
// ---------------------------------------------------------------------------
__global__ void zero_cnt_kernel(int* __restrict__ cnt, int M) {
    int i = blockIdx.x * blockDim.x + threadIdx.x;
    if (i < M) cnt[i] = 0;
}

__global__ void hist_kernel(const int* __restrict__ dst1,
                            const int* __restrict__ dst2,
                            int* __restrict__ cnt, int E, int N) {
    int i = blockIdx.x * blockDim.x + threadIdx.x;
    if (i < E)          atomicAdd(&cnt[dst1[i]], 1);
    else if (i < 2 * E) atomicAdd(&cnt[N + dst2[i - E]], 1);
}

__global__ void scan_partial_kernel(const int* __restrict__ cnt,
                                    int* __restrict__ partial, int M) {
    __shared__ int sdata[SCAN_BLK];
    int i = blockIdx.x * SCAN_BLK + threadIdx.x;
    sdata[threadIdx.x] = (i < M) ? cnt[i] : 0;
    __syncthreads();
    for (int s = SCAN_BLK / 2; s > 0; s >>= 1) {
        if (threadIdx.x < s) sdata[threadIdx.x] += sdata[threadIdx.x + s];
        __syncthreads();
    }
    if (threadIdx.x == 0) partial[blockIdx.x] = sdata[0];
}

__global__ void scan_mid_kernel(int* __restrict__ partial, int nb) {
    // single block, Hillis-Steele exclusive scan of nb (<=128) partials
    __shared__ int sdata[128];
    int v = (threadIdx.x < nb) ? partial[threadIdx.x] : 0;
    sdata[threadIdx.x] = v;
    __syncthreads();
    for (int s = 1; s < 128; s <<= 1) {
        int t = (threadIdx.x >= s) ? sdata[threadIdx.x - s] : 0;
        __syncthreads();
        sdata[threadIdx.x] += t;
        __syncthreads();
    }
    if (threadIdx.x < nb) partial[threadIdx.x] = sdata[threadIdx.x] - v; // exclusive
}

__global__ void scan_final_kernel(const int* __restrict__ cnt,
                                  const int* __restrict__ partial,
                                  int* __restrict__ ofs,
                                  int* __restrict__ cur,
                                  int M, int total) {
    __shared__ int sdata[SCAN_BLK];
    int i = blockIdx.x * SCAN_BLK + threadIdx.x;
    int v = (i < M) ? cnt[i] : 0;
    sdata[threadIdx.x] = v;
    __syncthreads();
    for (int s = 1; s < SCAN_BLK; s <<= 1) {
        int t = (threadIdx.x >= s) ? sdata[threadIdx.x - s] : 0;
        __syncthreads();
        sdata[threadIdx.x] += t;
        __syncthreads();
    }
    int excl = sdata[threadIdx.x] - v + partial[blockIdx.x];
    if (i < M) { ofs[i] = excl; cur[i] = excl; }
    if (i == M - 1) ofs[M] = total;
}

__global__ void fill_kernel(const int* __restrict__ src1,
                            const int* __restrict__ dst1,
                            const int* __restrict__ src2,
                            const int* __restrict__ dst2,
                            int* __restrict__ cur,
                            int2* __restrict__ sorted, int E, int N) {
    int i = blockIdx.x * blockDim.x + threadIdx.x;
    int e, d, s, bin;
    if (i < E) {
        e = i; d = dst1[e]; s = src1[e]; bin = d;
    } else if (i < 2 * E) {
        e = i - E; d = dst2[e]; s = src2[e]; bin = N + d;
    } else return;
    int pos = atomicAdd(&cur[bin], 1);
    sorted[pos] = make_int2(e, s);
}

// ---------------------------------------------------------------------------
// Gather-aggregate: one warp per (rel, node). Register accumulation, no
// atomics, no pre-zeroing. Edges batch-loaded (32 at a time, coalesced),
// each half-warp (16 lanes x float4 = full H row) processes alternate edges.
// ---------------------------------------------------------------------------
__global__ void gather_kernel(const float* __restrict__ h,
                              const float* __restrict__ feat1,
                              const float* __restrict__ feat2,
                              const int* __restrict__ ofs,
                              const int2* __restrict__ sorted,
                              float* __restrict__ acc_out,
                              int N) {
    int warp = blockIdx.x * (blockDim.x >> 5) + (threadIdx.x >> 5);
    if (warp >= 2 * N) return;

    const float* feat = (warp < N) ? feat1 : feat2;

    const int lane   = threadIdx.x & 31;
    const int lane16 = lane & 15;
    const int half   = lane >> 4;

    const int start = ofs[warp];
    const int end   = ofs[warp + 1];

    float4 acc = make_float4(0.f, 0.f, 0.f, 0.f);

    for (int bs = start; bs < end; bs += 32) {
        int nb = min(32, end - bs);
        int2 es = (lane < nb) ? sorted[bs + lane] : make_int2(0, 0);

        #pragma unroll 4
        for (int j2 = 0; j2 < nb; j2 += 2) {
            int j  = j2 + half;
            int jc = min(j, nb - 1);
            int e  = __shfl_sync(0xffffffffu, es.x, jc);
            int s  = __shfl_sync(0xffffffffu, es.y, jc);
            if (j < nb) {
                float4 f  = *(const float4*)(feat + (size_t)e * HH + lane16 * 4);
                float4 hv = *(const float4*)(h    + (size_t)s * HH + lane16 * 4);
                acc.x = fmaf(f.x, hv.x, acc.x);
                acc.y = fmaf(f.y, hv.y, acc.y);
                acc.z = fmaf(f.z, hv.z, acc.z);
                acc.w = fmaf(f.w, hv.w, acc.w);
            }
        }
    }

    // Combine the two half-warps (both accumulated the same bin)
    acc.x += __shfl_down_sync(0xffffffffu, acc.x, 16);
    acc.y += __shfl_down_sync(0xffffffffu, acc.y, 16);
    acc.z += __shfl_down_sync(0xffffffffu, acc.z, 16);
    acc.w += __shfl_down_sync(0xffffffffu, acc.w, 16);

    if (half == 0)
        ((float4*)(acc_out + (size_t)warp * HH))[lane16] = acc;
}

// ---------------------------------------------------------------------------
// Update: h_out = h_in + relu(concat(a1,a2) @ W + b)
// Register-tiled: 64 nodes x 64 cols block, 4x4 (float4) per thread.
// ---------------------------------------------------------------------------
#define APAD 132
#define UPD_SMEM_BYTES ((128 * 64 + 64 * APAD) * 4)

__global__ void update_kernel(const float* __restrict__ h_in,
                              const float* __restrict__ a1,
                              const float* __restrict__ a2,
                              const float* __restrict__ W,
                              const float* __restrict__ b,
                              float* __restrict__ h_out,
                              int N) {
    extern __shared__ float smem[];
    float* Ws = smem;                                        // [128][64]
    float (*As)[APAD] = (float (*)[APAD])(smem + 128 * 64);  // [64][APAD]

    const int tid = threadIdx.x;
    const int tc  = tid & 15;
    const int tn  = tid >> 4;

    for (int i = tid; i < 128 * 16; i += 256)
        ((float4*)Ws)[i] = ((const float4*)W)[i];

    const float4 bias = ((const float4*)b)[tc];
    const int base = blockIdx.x * 64;

    for (int i = tid; i < 2048; i += 256) {
        int node = i >> 5;
        int kq   = i & 31;
        int gn   = base + node;
        float4 v = make_float4(0.f, 0.f, 0.f, 0.f);
        if (gn < N) {
            if (kq < 16) v = ((const float4*)(a1 + (size_t)gn * HH))[kq];
            else         v = ((const float4*)(a2 + (size_t)gn * HH))[kq - 16];
        }
        *(float4*)&As[node][kq * 4] = v;
    }
    __syncthreads();

    float4 acc[4];
    #pragma unroll
    for (int i = 0; i < 4; i++) acc[i] = bias;

    #pragma unroll 4
    for (int k4 = 0; k4 < 32; k4++) {
        const int k = k4 * 4;
        float4 w0 = *(const float4*)&Ws[(k + 0) * 64 + tc * 4];
        float4 w1 = *(const float4*)&Ws[(k + 1) * 64 + tc * 4];
        float4 w2 = *(const float4*)&Ws[(k + 2) * 64 + tc * 4];
        float4 w3 = *(const float4*)&Ws[(k + 3) * 64 + tc * 4];
        #pragma unroll
        for (int i = 0; i < 4; i++) {
            float4 a = *(const float4*)&As[tn * 4 + i][k];
            acc[i].x = fmaf(a.w, w3.x, fmaf(a.z, w2.x, fmaf(a.y, w1.x, fmaf(a.x, w0.x, acc[i].x))));
            acc[i].y = fmaf(a.w, w3.y, fmaf(a.z, w2.y, fmaf(a.y, w1.y, fmaf(a.x, w0.y, acc[i].y))));
            acc[i].z = fmaf(a.w, w3.z, fmaf(a.z, w2.z, fmaf(a.y, w1.z, fmaf(a.x, w0.z, acc[i].z))));
            acc[i].w = fmaf(a.w, w3.w, fmaf(a.z, w2.w, fmaf(a.y, w1.w, fmaf(a.x, w0.w, acc[i].w))));
        }
    }

    #pragma unroll
    for (int i = 0; i < 4; i++) {
        int gn = base + tn * 4 + i;
        if (gn < N) {
            float4 hv = ((const float4*)(h_in + (size_t)gn * HH))[tc];
            float4 o;
            o.x = hv.x + fmaxf(acc[i].x, 0.f);
            o.y = hv.y + fmaxf(acc[i].y, 0.f);
            o.z = hv.z + fmaxf(acc[i].z, 0.f);
            o.w = hv.w + fmaxf(acc[i].w, 0.f);
            ((float4*)(h_out + (size_t)gn * HH))[tc] = o;
        }
    }
}

// ---------------------------------------------------------------------------
// Launch
// ---------------------------------------------------------------------------
extern "C" void kernel_launch(void* const* d_in, const int* in_sizes, int n_in,
                              void* d_out, int out_size) {
    const float* h0    = (const float*)d_in[0];
    const float* feat1 = (const float*)d_in[1];
    const float* feat2 = (const float*)d_in[2];
    const float* W1    = (const float*)d_in[3];
    const float* b1    = (const float*)d_in[4];
    const float* W2    = (const float*)d_in[5];
    const float* b2    = (const float*)d_in[6];
    const int*   src1  = (const int*)d_in[7];
    const int*   dst1  = (const int*)d_in[8];
    const int*   src2  = (const int*)d_in[9];
    const int*   dst2  = (const int*)d_in[10];
    float* out = (float*)d_out;

    const int N = in_sizes[0] / HH;   // 50000
    const int E = in_sizes[7];        // 800000
    const int M = 2 * N;

    float* acc_base; float* hbuf;
    int *cnt, *ofs, *cur, *part; int2* sorted;
    cudaGetSymbolAddress((void**)&acc_base, g_acc);
    cudaGetSymbolAddress((void**)&hbuf, g_h);
    cudaGetSymbolAddress((void**)&cnt, g_cnt);
    cudaGetSymbolAddress((void**)&ofs, g_ofs);
    cudaGetSymbolAddress((void**)&cur, g_cur);
    cudaGetSymbolAddress((void**)&part, g_part);
    cudaGetSymbolAddress((void**)&sorted, g_sorted);
    float* a1 = acc_base;
    float* a2 = acc_base + (size_t)N * HH;

    static bool attr_set = false;
    if (!attr_set) {
        cudaFuncSetAttribute(update_kernel,
                             cudaFuncAttributeMaxDynamicSharedMemorySize,
                             UPD_SMEM_BYTES);
        attr_set = true;
    }

    // ---- CSR build (once; shared by both layers) ----
    zero_cnt_kernel<<<(M + 255) / 256, 256>>>(cnt, M);
    hist_kernel<<<(2 * E + 255) / 256, 256>>>(dst1, dst2, cnt, E, N);
    const int nb = (M + SCAN_BLK - 1) / SCAN_BLK;
    scan_partial_kernel<<<nb, SCAN_BLK>>>(cnt, part, M);
    scan_mid_kernel<<<1, 128>>>(part, nb);
    scan_final_kernel<<<nb, SCAN_BLK>>>(cnt, part, ofs, cur, M, 2 * E);
    fill_kernel<<<(2 * E + 255) / 256, 256>>>(src1, dst1, src2, dst2, cur,
                                              sorted, E, N);

    const int ggrid = (M * 32 + 255) / 256;   // one warp per (rel,node)
    const int ugrid = (N + 63) / 64;

    // ---- Layer 1 ----
    gather_kernel<<<ggrid, 256>>>(h0, feat1, feat2, ofs, sorted, acc_base, N);
    update_kernel<<<ugrid, 256, UPD_SMEM_BYTES>>>(h0, a1, a2, W1, b1, hbuf, N);

    // ---- Layer 2 ----
    gather_kernel<<<ggrid, 256>>>(hbuf, feat1, feat2, ofs, sorted, acc_base, N);
    update_kernel<<<ugrid, 256, UPD_SMEM_BYTES>>>(hbuf, a1, a2, W2, b2, out, N);
}

// round 5
// speedup vs baseline: 1.5090x; 1.0564x over previous
#include <cuda_runtime.h>
#include <cstdint>

#define NN 50000
#define HH 64
#define EE 800000
#define MM (2 * NN)
#define SCAN_BLK 1024
#define NB ((MM + SCAN_BLK - 1) / SCAN_BLK)   // 98

// Scratch
__device__ float g_acc[2 * NN * HH];
__device__ float g_h[NN * HH];
__device__ int   g_cnt[MM];
__device__ int   g_ofs[MM + 1];
__device__ int   g_cur[MM];
__device__ int   g_part[NB + 1];
__device__ int2  g_sorted[2 * EE];

// ---------------------------------------------------------------------------
// CSR build
// ---------------------------------------------------------------------------
__global__ void zero_cnt_kernel(int* __restrict__ cnt, int M) {
    int i = blockIdx.x * blockDim.x + threadIdx.x;
    if (i < M) cnt[i] = 0;
}

__global__ void hist_kernel(const int* __restrict__ dst1,
                            const int* __restrict__ dst2,
                            int* __restrict__ cnt, int E, int N) {
    int i = blockIdx.x * blockDim.x + threadIdx.x;
    if (i < E)          atomicAdd(&cnt[dst1[i]], 1);
    else if (i < 2 * E) atomicAdd(&cnt[N + dst2[i - E]], 1);
}

__global__ void scan_partial_kernel(const int* __restrict__ cnt,
                                    int* __restrict__ partial, int M) {
    __shared__ int sdata[SCAN_BLK];
    int i = blockIdx.x * SCAN_BLK + threadIdx.x;
    sdata[threadIdx.x] = (i < M) ? cnt[i] : 0;
    __syncthreads();
    for (int s = SCAN_BLK / 2; s > 0; s >>= 1) {
        if (threadIdx.x < s) sdata[threadIdx.x] += sdata[threadIdx.x + s];
        __syncthreads();
    }
    if (threadIdx.x == 0) partial[blockIdx.x] = sdata[0];
}

// Final scan: every block redundantly scans the (<=128) block partials in
// smem, then does its own 1024-wide scan. Replaces the old scan_mid kernel.
__global__ void scan_final_kernel(const int* __restrict__ cnt,
                                  const int* __restrict__ partial,
                                  int* __restrict__ ofs,
                                  int* __restrict__ cur,
                                  int M, int total, int nb) {
    __shared__ int pscan[128];
    __shared__ int sdata[SCAN_BLK];

    if (threadIdx.x < 128)
        pscan[threadIdx.x] = (threadIdx.x < nb) ? partial[threadIdx.x] : 0;
    __syncthreads();
    for (int s = 1; s < 128; s <<= 1) {
        int t = 0;
        if (threadIdx.x < 128 && threadIdx.x >= s) t = pscan[threadIdx.x - s];
        __syncthreads();
        if (threadIdx.x < 128) pscan[threadIdx.x] += t;
        __syncthreads();
    }
    int block_prefix = (blockIdx.x == 0) ? 0 : pscan[blockIdx.x - 1];

    int i = blockIdx.x * SCAN_BLK + threadIdx.x;
    int v = (i < M) ? cnt[i] : 0;
    sdata[threadIdx.x] = v;
    __syncthreads();
    for (int s = 1; s < SCAN_BLK; s <<= 1) {
        int t = (threadIdx.x >= s) ? sdata[threadIdx.x - s] : 0;
        __syncthreads();
        sdata[threadIdx.x] += t;
        __syncthreads();
    }
    int excl = sdata[threadIdx.x] - v + block_prefix;
    if (i < M) { ofs[i] = excl; cur[i] = excl; }
    if (i == M - 1) ofs[M] = total;
}

__global__ void fill_kernel(const int* __restrict__ src1,
                            const int* __restrict__ dst1,
                            const int* __restrict__ src2,
                            const int* __restrict__ dst2,
                            int* __restrict__ cur,
                            int2* __restrict__ sorted, int E, int N) {
    int i = blockIdx.x * blockDim.x + threadIdx.x;
    int e, s, bin;
    if (i < E) {
        e = i; bin = dst1[e]; s = src1[e];
    } else if (i < 2 * E) {
        e = i - E; bin = N + dst2[e]; s = src2[e];
    } else return;
    int pos = atomicAdd(&cur[bin], 1);
    sorted[pos] = make_int2(e, s);
}

// ---------------------------------------------------------------------------
// Gather-aggregate: one warp per (rel, node) bin. 4 edges processed per
// warp-step (8 lanes x 2 float4 per edge). feat read with __ldcs (evict-
// first) so h / sorted / acc stay L2-resident. No atomics, no pre-zeroing.
// ---------------------------------------------------------------------------
#define FMA4(acc, f, hv)                         \
    acc.x = fmaf(f.x, hv.x, acc.x);              \
    acc.y = fmaf(f.y, hv.y, acc.y);              \
    acc.z = fmaf(f.z, hv.z, acc.z);              \
    acc.w = fmaf(f.w, hv.w, acc.w);

__global__ void gather_kernel(const float* __restrict__ h,
                              const float* __restrict__ feat1,
                              const float* __restrict__ feat2,
                              const int* __restrict__ ofs,
                              const int2* __restrict__ sorted,
                              float* __restrict__ acc_out,
                              int N) {
    int warp = blockIdx.x * (blockDim.x >> 5) + (threadIdx.x >> 5);
    if (warp >= 2 * N) return;

    const float* feat = (warp < N) ? feat1 : feat2;
    const int lane = threadIdx.x & 31;
    const int eg   = lane >> 3;   // edge subgroup 0..3
    const int k8   = lane & 7;    // float4 index within half-row

    const int start = ofs[warp];
    const int end   = ofs[warp + 1];

    float4 acc0 = make_float4(0.f, 0.f, 0.f, 0.f);
    float4 acc1 = make_float4(0.f, 0.f, 0.f, 0.f);

    for (int bs = start; bs < end; bs += 32) {
        int nb = min(32, end - bs);
        int2 es = make_int2(0, 0);
        if (lane < nb) es = sorted[bs + lane];

        #pragma unroll 2
        for (int j4 = 0; j4 < nb; j4 += 4) {
            int j  = j4 + eg;
            int jc = min(j, nb - 1);
            int e  = __shfl_sync(0xffffffffu, es.x, jc);
            int s  = __shfl_sync(0xffffffffu, es.y, jc);
            const float4* fp = (const float4*)(feat + (size_t)e * HH);
            const float4* hp = (const float4*)(h    + (size_t)s * HH);
            float4 f0 = __ldcs(fp + k8);
            float4 f1 = __ldcs(fp + k8 + 8);
            float4 h0 = hp[k8];
            float4 h1 = hp[k8 + 8];
            if (j < nb) {
                FMA4(acc0, f0, h0);
                FMA4(acc1, f1, h1);
            }
        }
    }

    // Reduce the 4 edge subgroups (same k8 positions) onto lanes 0..7
    #pragma unroll
    for (int off = 16; off >= 8; off >>= 1) {
        acc0.x += __shfl_down_sync(0xffffffffu, acc0.x, off);
        acc0.y += __shfl_down_sync(0xffffffffu, acc0.y, off);
        acc0.z += __shfl_down_sync(0xffffffffu, acc0.z, off);
        acc0.w += __shfl_down_sync(0xffffffffu, acc0.w, off);
        acc1.x += __shfl_down_sync(0xffffffffu, acc1.x, off);
        acc1.y += __shfl_down_sync(0xffffffffu, acc1.y, off);
        acc1.z += __shfl_down_sync(0xffffffffu, acc1.z, off);
        acc1.w += __shfl_down_sync(0xffffffffu, acc1.w, off);
    }

    if (lane < 8) {
        float4* op = (float4*)(acc_out + (size_t)warp * HH);
        op[k8]     = acc0;
        op[k8 + 8] = acc1;
    }
}

// ---------------------------------------------------------------------------
// Update: h_out = h_in + relu(concat(a1,a2) @ W + b)
// ---------------------------------------------------------------------------
#define APAD 132
#define UPD_SMEM_BYTES ((128 * 64 + 64 * APAD) * 4)

__global__ void update_kernel(const float* __restrict__ h_in,
                              const float* __restrict__ a1,
                              const float* __restrict__ a2,
                              const float* __restrict__ W,
                              const float* __restrict__ b,
                              float* __restrict__ h_out,
                              int N) {
    extern __shared__ float smem[];
    float* Ws = smem;
    float (*As)[APAD] = (float (*)[APAD])(smem + 128 * 64);

    const int tid = threadIdx.x;
    const int tc  = tid & 15;
    const int tn  = tid >> 4;

    for (int i = tid; i < 128 * 16; i += 256)
        ((float4*)Ws)[i] = ((const float4*)W)[i];

    const float4 bias = ((const float4*)b)[tc];
    const int base = blockIdx.x * 64;

    for (int i = tid; i < 2048; i += 256) {
        int node = i >> 5;
        int kq   = i & 31;
        int gn   = base + node;
        float4 v = make_float4(0.f, 0.f, 0.f, 0.f);
        if (gn < N) {
            if (kq < 16) v = ((const float4*)(a1 + (size_t)gn * HH))[kq];
            else         v = ((const float4*)(a2 + (size_t)gn * HH))[kq - 16];
        }
        *(float4*)&As[node][kq * 4] = v;
    }
    __syncthreads();

    float4 acc[4];
    #pragma unroll
    for (int i = 0; i < 4; i++) acc[i] = bias;

    #pragma unroll 4
    for (int k4 = 0; k4 < 32; k4++) {
        const int k = k4 * 4;
        float4 w0 = *(const float4*)&Ws[(k + 0) * 64 + tc * 4];
        float4 w1 = *(const float4*)&Ws[(k + 1) * 64 + tc * 4];
        float4 w2 = *(const float4*)&Ws[(k + 2) * 64 + tc * 4];
        float4 w3 = *(const float4*)&Ws[(k + 3) * 64 + tc * 4];
        #pragma unroll
        for (int i = 0; i < 4; i++) {
            float4 a = *(const float4*)&As[tn * 4 + i][k];
            acc[i].x = fmaf(a.w, w3.x, fmaf(a.z, w2.x, fmaf(a.y, w1.x, fmaf(a.x, w0.x, acc[i].x))));
            acc[i].y = fmaf(a.w, w3.y, fmaf(a.z, w2.y, fmaf(a.y, w1.y, fmaf(a.x, w0.y, acc[i].y))));
            acc[i].z = fmaf(a.w, w3.z, fmaf(a.z, w2.z, fmaf(a.y, w1.z, fmaf(a.x, w0.z, acc[i].z))));
            acc[i].w = fmaf(a.w, w3.w, fmaf(a.z, w2.w, fmaf(a.y, w1.w, fmaf(a.x, w0.w, acc[i].w))));
        }
    }

    #pragma unroll
    for (int i = 0; i < 4; i++) {
        int gn = base + tn * 4 + i;
        if (gn < N) {
            float4 hv = ((const float4*)(h_in + (size_t)gn * HH))[tc];
            float4 o;
            o.x = hv.x + fmaxf(acc[i].x, 0.f);
            o.y = hv.y + fmaxf(acc[i].y, 0.f);
            o.z = hv.z + fmaxf(acc[i].z, 0.f);
            o.w = hv.w + fmaxf(acc[i].w, 0.f);
            ((float4*)(h_out + (size_t)gn * HH))[tc] = o;
        }
    }
}

// ---------------------------------------------------------------------------
// Launch
// ---------------------------------------------------------------------------
extern "C" void kernel_launch(void* const* d_in, const int* in_sizes, int n_in,
                              void* d_out, int out_size) {
    const float* h0    = (const float*)d_in[0];
    const float* feat1 = (const float*)d_in[1];
    const float* feat2 = (const float*)d_in[2];
    const float* W1    = (const float*)d_in[3];
    const float* b1    = (const float*)d_in[4];
    const float* W2    = (const float*)d_in[5];
    const float* b2    = (const float*)d_in[6];
    const int*   src1  = (const int*)d_in[7];
    const int*   dst1  = (const int*)d_in[8];
    const int*   src2  = (const int*)d_in[9];
    const int*   dst2  = (const int*)d_in[10];
    float* out = (float*)d_out;

    const int N = in_sizes[0] / HH;
    const int E = in_sizes[7];
    const int M = 2 * N;

    float* acc_base; float* hbuf;
    int *cnt, *ofs, *cur, *part; int2* sorted;
    cudaGetSymbolAddress((void**)&acc_base, g_acc);
    cudaGetSymbolAddress((void**)&hbuf, g_h);
    cudaGetSymbolAddress((void**)&cnt, g_cnt);
    cudaGetSymbolAddress((void**)&ofs, g_ofs);
    cudaGetSymbolAddress((void**)&cur, g_cur);
    cudaGetSymbolAddress((void**)&part, g_part);
    cudaGetSymbolAddress((void**)&sorted, g_sorted);
    float* a1 = acc_base;
    float* a2 = acc_base + (size_t)N * HH;

    static bool attr_set = false;
    if (!attr_set) {
        cudaFuncSetAttribute(update_kernel,
                             cudaFuncAttributeMaxDynamicSharedMemorySize,
                             UPD_SMEM_BYTES);
        attr_set = true;
    }

    // ---- CSR build (once; shared by both layers) ----
    zero_cnt_kernel<<<(M + 255) / 256, 256>>>(cnt, M);
    hist_kernel<<<(2 * E + 255) / 256, 256>>>(dst1, dst2, cnt, E, N);
    const int nb = (M + SCAN_BLK - 1) / SCAN_BLK;
    scan_partial_kernel<<<nb, SCAN_BLK>>>(cnt, part, M);
    scan_final_kernel<<<nb, SCAN_BLK>>>(cnt, part, ofs, cur, M, 2 * E, nb);
    fill_kernel<<<(2 * E + 255) / 256, 256>>>(src1, dst1, src2, dst2, cur,
                                              sorted, E, N);

    const int ggrid = (M * 32 + 255) / 256;
    const int ugrid = (N + 63) / 64;

    // ---- Layer 1 ----
    gather_kernel<<<ggrid, 256>>>(h0, feat1, feat2, ofs, sorted, acc_base, N);
    update_kernel<<<ugrid, 256, UPD_SMEM_BYTES>>>(h0, a1, a2, W1, b1, hbuf, N);

    // ---- Layer 2 ----
    gather_kernel<<<ggrid, 256>>>(hbuf, feat1, feat2, ofs, sorted, acc_base, N);
    update_kernel<<<ugrid, 256, UPD_SMEM_BYTES>>>(hbuf, a1, a2, W2, b2, out, N);
}